// round 4
// baseline (speedup 1.0000x reference)
#include <cuda_runtime.h>
#include <stdint.h>

#define IW 1024
#define IH 1024
#define NIMG 8
#define PLANE (IW*IH)
#define NP (NIMG*PLANE)

// tile: 64 wide x 32 high
#define TW 64
#define TH 32
// smem region sizes
#define GYW 72          // gray width  (TW+8)
#define GYH 40          // gray height (TH+8)
#define HBW 68          // hblur width (TW+4)
#define MGW 66          // mag width   (TW+2)

// ---- persistent scratch ----
__device__ unsigned char g_code[NP];
__device__ int           g_lab[NP];
__device__ unsigned char g_flag[NP];

__device__ __constant__ float GW[5] = {
    0.0544886855f, 0.2442013420f, 0.4026199447f, 0.2442013420f, 0.0544886855f };

__device__ __constant__ int NDY[8] = {0,-1,-1,-1, 0, 1, 1, 1};
__device__ __constant__ int NDX[8] = {1, 1, 0,-1,-1,-1, 0, 1};

// ---------- shared-memory union-find ----------
__device__ __forceinline__ int rep_s(volatile int* L, int x) {
    int r = L[x];
    int p = L[r];
    while (p != r) { r = p; p = L[r]; }
    return r;
}
__device__ __forceinline__ void unite_s(int* L, int a, int b) {
    volatile int* Lv = L;
    int ra = rep_s(Lv, a), rb = rep_s(Lv, b);
    while (ra != rb) {
        if (ra < rb) { int t = ra; ra = rb; rb = t; }
        int old = atomicMin(&L[ra], rb);
        if (old == ra) break;
        ra = rep_s(Lv, old);
        rb = rep_s(Lv, rb);
    }
}

// ---------- global union-find ----------
__device__ __forceinline__ int uf_rep(int x) {
    volatile int* L = g_lab;
    int r = L[x];
    int p = L[r];
    while (p != r) { r = p; p = L[r]; }
    return r;
}
__device__ __forceinline__ void uf_unite(int a, int b) {
    int ra = uf_rep(a), rb = uf_rep(b);
    while (ra != rb) {
        if (ra < rb) { int t = ra; ra = rb; rb = t; }
        int old = atomicMin(&g_lab[ra], rb);
        if (old == ra) break;
        ra = uf_rep(old);
        rb = uf_rep(rb);
    }
}

// =================================================================
// Fused front (64x32 tile, 256 threads, 8 px/thread)
// =================================================================
__global__ __launch_bounds__(256) void k_front(const float* __restrict__ img,
                                               float* __restrict__ out_mag) {
    __shared__ float A[GYH*GYW];              // gray -> (aliased) L
    __shared__ float B[GYH*HBW];              // hblur -> mag
    __shared__ float V[(TH+4)*HBW];           // vblur (36x68)
    __shared__ unsigned char DIR[TH*TW];
    __shared__ unsigned char C[TH*TW];
    int* L = reinterpret_cast<int*>(A);       // 2048 ints = 8KB <= 11.5KB

    const int tid = threadIdx.x;
    const int x0 = blockIdx.x * TW;
    const int y0 = blockIdx.y * TH;
    const int n  = blockIdx.z;
    const float* rch = img + (size_t)n * 3 * PLANE;
    const float* gch = rch + PLANE;
    const float* bch = gch + PLANE;

    // ---- stage 1: gray (40x72), reflect pad ----
#pragma unroll
    for (int it = 0; it < (GYH*GYW + 255)/256; it++) {
        int i = tid + it*256;
        if (i < GYH*GYW) {
            int ly = i / GYW, lx = i - ly*GYW;
            int gy = y0 + ly - 4;
            int gx = x0 + lx - 4;
            gy = (gy < 0) ? -gy : ((gy >= IH) ? 2*IH - 2 - gy : gy);
            gx = (gx < 0) ? -gx : ((gx >= IW) ? 2*IW - 2 - gx : gx);
            int o = (gy << 10) + gx;
            A[i] = 0.299f * rch[o] + 0.587f * gch[o] + 0.114f * bch[o];
        }
    }
    __syncthreads();

    // ---- stage 2: horizontal blur (40x68) ----
#pragma unroll
    for (int it = 0; it < (GYH*HBW + 255)/256; it++) {
        int i = tid + it*256;
        if (i < GYH*HBW) {
            int ly = i / HBW, hx = i - ly*HBW;
            float acc = 0.f;
#pragma unroll
            for (int k = 0; k < 5; k++)
                acc = fmaf(GW[k], A[ly*GYW + hx + k], acc);
            B[i] = acc;
        }
    }
    __syncthreads();

    // ---- stage 3: vertical blur (36x68) ----
#pragma unroll
    for (int it = 0; it < ((TH+4)*HBW + 255)/256; it++) {
        int i = tid + it*256;
        if (i < (TH+4)*HBW) {
            int by = i / HBW, bx = i - by*HBW;
            float acc = 0.f;
#pragma unroll
            for (int k = 0; k < 5; k++)
                acc = fmaf(GW[k], B[(by + k)*HBW + bx], acc);
            V[i] = acc;
        }
    }
    __syncthreads();

    // ---- stage 4: sobel + magnitude (34x66) into B, dir (32x64) ----
#pragma unroll
    for (int it = 0; it < ((TH+2)*MGW + 255)/256; it++) {
        int i = tid + it*256;
        if (i < (TH+2)*MGW) {
            int my = i / MGW, mx = i - my*MGW;
            int gy = y0 + my - 1;
            int gx = x0 + mx - 1;
            float m = 0.f;
            if (gy >= 0 && gy < IH && gx >= 0 && gx < IW) {
                int ym = (gy > 0)    ? gy - 1 : 0;
                int yp = (gy < IH-1) ? gy + 1 : IH - 1;
                int xm = (gx > 0)    ? gx - 1 : 0;
                int xp = (gx < IW-1) ? gx + 1 : IW - 1;
                int lym = ym - y0 + 2, lyc = gy - y0 + 2, lyp = yp - y0 + 2;
                int lxm = xm - x0 + 2, lxc = gx - x0 + 2, lxp = xp - x0 + 2;
                float a = V[lym*HBW+lxm], b = V[lym*HBW+lxc], c = V[lym*HBW+lxp];
                float d = V[lyc*HBW+lxm],                      e = V[lyc*HBW+lxp];
                float f = V[lyp*HBW+lxm], g = V[lyp*HBW+lxc], h = V[lyp*HBW+lxp];
                float gxv = (c - a) + 2.f * (e - d) + (h - f);
                float gyv = (f - a) + 2.f * (g - b) + (h - c);
                m = sqrtf(gxv * gxv + gyv * gyv + 1e-6f);
                if (my >= 1 && my <= TH && mx >= 1 && mx <= TW) {
                    float deg = atan2f(gyv, gxv) * 57.29577951308232f;
                    int itg = (int)rintf(deg / 45.0f);
                    DIR[(my-1)*TW + (mx-1)] = (unsigned char)((itg + 8) & 7);
                }
            }
            B[i] = m;
        }
    }
    __syncthreads();

    // ---- stage 5: NMS + thresholds; seed local CCL ----
#pragma unroll
    for (int it = 0; it < (TH*TW)/256; it++) {
        int i = tid + it*256;
        int cy = i >> 6, cx = i & (TW-1);
        int my = cy + 1, mx = cx + 1;
        float m = B[my*MGW + mx];
        int d  = DIR[i];
        int d2 = (d + 4) & 7;
        float mp = B[(my + NDY[d ])*MGW + (mx + NDX[d ])];
        float mn = B[(my + NDY[d2])*MGW + (mx + NDX[d2])];
        bool keep = ((m - mp) > 0.f) && ((m - mn) > 0.f);
        float mo = keep ? m : 0.f;
        unsigned char code = (unsigned char)((mo > 0.1f ? 1 : 0) + (mo > 0.2f ? 1 : 0));
        int gy = y0 + cy, gx = x0 + cx;
        int idx = n * PLANE + (gy << 10) + gx;
        out_mag[idx] = mo;
        g_code[idx]  = code;
        C[i] = code;
        L[i] = i;
    }
    __syncthreads();

    // ---- stage 6: tile-local union-find hooking (32x64) ----
#pragma unroll
    for (int it = 0; it < (TH*TW)/256; it++) {
        int i = tid + it*256;
        if (!C[i]) continue;
        int cx = i & (TW-1), cy = i >> 6;
        if (cx < TW-1 && C[i + 1])      unite_s(L, i, i + 1);
        if (cy < TH-1) {
            if (cx > 0    && C[i + TW - 1]) unite_s(L, i, i + TW - 1);
            if (             C[i + TW    ]) unite_s(L, i, i + TW);
            if (cx < TW-1 && C[i + TW + 1]) unite_s(L, i, i + TW + 1);
        }
    }
    __syncthreads();

    // ---- stage 7: resolve tile roots, write global labels ----
#pragma unroll
    for (int it = 0; it < (TH*TW)/256; it++) {
        int i = tid + it*256;
        if (!C[i]) continue;
        int r = i, p = L[r];
        while (p != r) { r = p; p = L[r]; }
        int gy = y0 + (i >> 6), gx = x0 + (i & (TW-1));
        int idx = n * PLANE + (gy << 10) + gx;
        int ry = y0 + (r >> 6), rx = x0 + (r & (TW-1));
        g_lab[idx]  = n * PLANE + (ry << 10) + rx;
        g_flag[idx] = 0;
    }
}

// =================================================================
// Boundary merge: tile edges only (rows y=32b+31, cols x=64b+63)
// =================================================================
#define NHROW 31            // horizontal boundary rows per image
#define NVCOL 15            // vertical boundary cols per image
#define PER_IMG ((NHROW + NVCOL)*1024)
__global__ __launch_bounds__(256) void k_boundary() {
    int t = blockIdx.x * blockDim.x + threadIdx.x;
    if (t >= NIMG * PER_IMG) return;
    int n = t / PER_IMG;
    int r = t - n * PER_IMG;
    int base = n * PLANE;
    if (r < NHROW*1024) {
        int b = r >> 10, x = r & 1023;
        int y = TH*b + (TH-1);
        int i = base + (y << 10) + x;
        if (!g_code[i]) return;
        int j = i + IW;
        if (x > 0    && g_code[j - 1]) uf_unite(i, j - 1);
        if (            g_code[j    ]) uf_unite(i, j);
        if (x < 1023 && g_code[j + 1]) uf_unite(i, j + 1);
    } else {
        r -= NHROW*1024;
        int b = r >> 10, y = r & 1023;
        int x = TW*b + (TW-1);
        int i = base + (y << 10) + x;
        if (!g_code[i]) return;
        if (g_code[i + 1]) uf_unite(i, i + 1);
        if ((y & (TH-1)) != 0    && g_code[i + 1 - IW]) uf_unite(i, i + 1 - IW);
        if ((y & (TH-1)) != TH-1 && g_code[i + 1 + IW]) uf_unite(i, i + 1 + IW);
    }
}

// =================================================================
__global__ __launch_bounds__(256) void k_flatten() {
    int t = blockIdx.x * blockDim.x + threadIdx.x;
    if (t >= NP/4) return;
    uchar4 c = reinterpret_cast<const uchar4*>(g_code)[t];
    int i0 = t * 4;
    if (c.x) { int r = uf_rep(i0);   g_lab[i0]   = r; if (c.x == 2) g_flag[r] = 1; }
    if (c.y) { int r = uf_rep(i0+1); g_lab[i0+1] = r; if (c.y == 2) g_flag[r] = 1; }
    if (c.z) { int r = uf_rep(i0+2); g_lab[i0+2] = r; if (c.z == 2) g_flag[r] = 1; }
    if (c.w) { int r = uf_rep(i0+3); g_lab[i0+3] = r; if (c.w == 2) g_flag[r] = 1; }
}

__global__ __launch_bounds__(256) void k_final(float* __restrict__ out_hyst) {
    int t = blockIdx.x * blockDim.x + threadIdx.x;
    if (t >= NP/4) return;
    uchar4 c = reinterpret_cast<const uchar4*>(g_code)[t];
    int i0 = t * 4;
    float4 v = make_float4(0.f, 0.f, 0.f, 0.f);
    if (c.x && g_flag[g_lab[i0  ]]) v.x = 1.f;
    if (c.y && g_flag[g_lab[i0+1]]) v.y = 1.f;
    if (c.z && g_flag[g_lab[i0+2]]) v.z = 1.f;
    if (c.w && g_flag[g_lab[i0+3]]) v.w = 1.f;
    reinterpret_cast<float4*>(out_hyst)[t] = v;
}

// =================================================================
extern "C" void kernel_launch(void* const* d_in, const int* in_sizes, int n_in,
                              void* d_out, int out_size) {
    const float* img = (const float*)d_in[0];
    float* out = (float*)d_out;

    dim3 fgrid(IW/TW, IH/TH, NIMG);
    k_front<<<fgrid, 256>>>(img, out);

    const int T = 256;
    k_boundary<<<(NIMG*PER_IMG + T - 1)/T, T>>>();
    k_flatten<<<(NP/4 + T - 1)/T, T>>>();
    k_final<<<(NP/4 + T - 1)/T, T>>>(out + NP);
}

// round 5
// speedup vs baseline: 1.8032x; 1.8032x over previous
#include <cuda_runtime.h>
#include <stdint.h>

#define IW 1024
#define IH 1024
#define NIMG 8
#define PLANE (IW*IH)
#define NP (NIMG*PLANE)

// ---- persistent scratch ----
__device__ unsigned char g_code[NP];
__device__ int           g_lab[NP];
__device__ unsigned char g_flag[NP];

__device__ __constant__ float GW[5] = {
    0.0544886855f, 0.2442013420f, 0.4026199447f, 0.2442013420f, 0.0544886855f };

__device__ __constant__ int NDY[8] = {0,-1,-1,-1, 0, 1, 1, 1};
__device__ __constant__ int NDX[8] = {1, 1, 0,-1,-1,-1, 0, 1};

// ---------- shared-memory union-find ----------
__device__ __forceinline__ int rep_s(volatile int* L, int x) {
    int r = L[x];
    int p = L[r];
    while (p != r) { r = p; p = L[r]; }
    return r;
}
__device__ __forceinline__ void unite_s(int* L, int a, int b) {
    volatile int* Lv = L;
    int ra = rep_s(Lv, a), rb = rep_s(Lv, b);
    while (ra != rb) {
        if (ra < rb) { int t = ra; ra = rb; rb = t; }
        int old = atomicMin(&L[ra], rb);
        if (old == ra) break;
        ra = rep_s(Lv, old);
        rb = rep_s(Lv, rb);
    }
}

// ---------- global union-find ----------
__device__ __forceinline__ int uf_rep(int x) {
    volatile int* L = g_lab;
    int r = L[x];
    int p = L[r];
    while (p != r) { r = p; p = L[r]; }
    return r;
}
__device__ __forceinline__ void uf_unite(int a, int b) {
    int ra = uf_rep(a), rb = uf_rep(b);
    while (ra != rb) {
        if (ra < rb) { int t = ra; ra = rb; rb = t; }
        int old = atomicMin(&g_lab[ra], rb);
        if (old == ra) break;
        ra = uf_rep(old);
        rb = uf_rep(rb);
    }
}

// =================================================================
// Fused front (32x32 tile, 256 threads) — R3 structure, division-free
// thread decomposition: ty = tid>>5 (0..7), tx = tid&31
// =================================================================
__global__ __launch_bounds__(256) void k_front(const float* __restrict__ img,
                                               float* __restrict__ out_mag) {
    __shared__ float A[40*40];            // gray, then vblur (36x36)
    __shared__ float B[40*36];            // hblur, then mag (34x34)
    __shared__ unsigned char DIR[32*32];
    __shared__ unsigned char C[32*32];
    __shared__ int L[32*32];

    const int tid = threadIdx.x;
    const int ty = tid >> 5;
    const int tx = tid & 31;
    const int x0 = blockIdx.x * 32;
    const int y0 = blockIdx.y * 32;
    const int n  = blockIdx.z;
    const float* rch = img + (size_t)n * 3 * PLANE;
    const float* gch = rch + PLANE;
    const float* bch = gch + PLANE;

    // ---- stage 1: gray (40x40), reflect pad ----
    for (int ry = ty; ry < 40; ry += 8) {
        int gy = y0 + ry - 4;
        gy = (gy < 0) ? -gy : ((gy >= IH) ? 2*IH - 2 - gy : gy);
        int rowo = gy << 10;
        for (int cx = tx; cx < 40; cx += 32) {
            int gx = x0 + cx - 4;
            gx = (gx < 0) ? -gx : ((gx >= IW) ? 2*IW - 2 - gx : gx);
            int o = rowo + gx;
            A[ry*40 + cx] = 0.299f * rch[o] + 0.587f * gch[o] + 0.114f * bch[o];
        }
    }
    __syncthreads();

    // ---- stage 2: horizontal blur (40 rows x 36 cols) ----
    for (int ry = ty; ry < 40; ry += 8) {
        for (int cx = tx; cx < 36; cx += 32) {
            float acc = 0.f;
#pragma unroll
            for (int k = 0; k < 5; k++)
                acc = fmaf(GW[k], A[ry*40 + cx + k], acc);
            B[ry*36 + cx] = acc;
        }
    }
    __syncthreads();

    // ---- stage 3: vertical blur (36x36) into A ----
    for (int ry = ty; ry < 36; ry += 8) {
        for (int cx = tx; cx < 36; cx += 32) {
            float acc = 0.f;
#pragma unroll
            for (int k = 0; k < 5; k++)
                acc = fmaf(GW[k], B[(ry + k)*36 + cx], acc);
            A[ry*36 + cx] = acc;
        }
    }
    __syncthreads();

    // ---- stage 4: sobel + magnitude (34x34) into B, dir (32x32) ----
    for (int ry = ty; ry < 34; ry += 8) {
        int gy = y0 + ry - 1;
        for (int cx = tx; cx < 34; cx += 32) {
            int gx = x0 + cx - 1;
            float m = 0.f;
            if (gy >= 0 && gy < IH && gx >= 0 && gx < IW) {
                int ym = (gy > 0)    ? gy - 1 : 0;
                int yp = (gy < IH-1) ? gy + 1 : IH - 1;
                int xm = (gx > 0)    ? gx - 1 : 0;
                int xp = (gx < IW-1) ? gx + 1 : IW - 1;
                int lym = ym - y0 + 2, lyc = gy - y0 + 2, lyp = yp - y0 + 2;
                int lxm = xm - x0 + 2, lxc = gx - x0 + 2, lxp = xp - x0 + 2;
                float a = A[lym*36+lxm], b = A[lym*36+lxc], c = A[lym*36+lxp];
                float d = A[lyc*36+lxm],                     e = A[lyc*36+lxp];
                float f = A[lyp*36+lxm], g = A[lyp*36+lxc], h = A[lyp*36+lxp];
                float gxv = (c - a) + 2.f * (e - d) + (h - f);
                float gyv = (f - a) + 2.f * (g - b) + (h - c);
                m = sqrtf(gxv * gxv + gyv * gyv + 1e-6f);
                if (ry >= 1 && ry <= 32 && cx >= 1 && cx <= 32) {
                    float deg = atan2f(gyv, gxv) * 57.29577951308232f;
                    int it = (int)rintf(deg / 45.0f);
                    DIR[(ry-1)*32 + (cx-1)] = (unsigned char)((it + 8) & 7);
                }
            }
            B[ry*34 + cx] = m;
        }
    }
    __syncthreads();

    // ---- stage 5: NMS + thresholds; seed local CCL ----
    for (int cy = ty; cy < 32; cy += 8) {
        int i = cy*32 + tx;
        int my = cy + 1, mx = tx + 1;
        float m = B[my*34 + mx];
        int d  = DIR[i];
        int d2 = (d + 4) & 7;
        float mp = B[(my + NDY[d ])*34 + (mx + NDX[d ])];
        float mn = B[(my + NDY[d2])*34 + (mx + NDX[d2])];
        bool keep = ((m - mp) > 0.f) && ((m - mn) > 0.f);
        float mo = keep ? m : 0.f;
        unsigned char code = (unsigned char)((mo > 0.1f ? 1 : 0) + (mo > 0.2f ? 1 : 0));
        int gy = y0 + cy, gx = x0 + tx;
        int idx = n * PLANE + (gy << 10) + gx;
        out_mag[idx] = mo;
        g_code[idx]  = code;
        C[i] = code;
        L[i] = i;
    }
    __syncthreads();

    // ---- stage 6: tile-local union-find hooking ----
    for (int cy = ty; cy < 32; cy += 8) {
        int i = cy*32 + tx;
        if (!C[i]) continue;
        if (tx < 31 && C[i + 1])  unite_s(L, i, i + 1);
        if (cy < 31) {
            if (tx > 0  && C[i + 31]) unite_s(L, i, i + 31);
            if (           C[i + 32]) unite_s(L, i, i + 32);
            if (tx < 31 && C[i + 33]) unite_s(L, i, i + 33);
        }
    }
    __syncthreads();

    // ---- stage 7: resolve tile roots, write global labels ----
    for (int cy = ty; cy < 32; cy += 8) {
        int i = cy*32 + tx;
        if (!C[i]) continue;
        int r = i, p = L[r];
        while (p != r) { r = p; p = L[r]; }
        int gy = y0 + cy, gx = x0 + tx;
        int idx = n * PLANE + (gy << 10) + gx;
        int ry = y0 + (r >> 5), rx = x0 + (r & 31);
        g_lab[idx]  = n * PLANE + (ry << 10) + rx;
        g_flag[idx] = 0;
    }
}

// =================================================================
// Boundary merge: tile edges only
// =================================================================
#define PER_IMG (31*1024*2)
__global__ __launch_bounds__(256) void k_boundary() {
    int t = blockIdx.x * blockDim.x + threadIdx.x;
    if (t >= NIMG * PER_IMG) return;
    int n = t / PER_IMG;
    int r = t - n * PER_IMG;
    int base = n * PLANE;
    if (r < 31*1024) {
        int b = r >> 10, x = r & 1023;
        int y = 32*b + 31;
        int i = base + (y << 10) + x;
        if (!g_code[i]) return;
        int j = i + IW;
        if (x > 0    && g_code[j - 1]) uf_unite(i, j - 1);
        if (            g_code[j    ]) uf_unite(i, j);
        if (x < 1023 && g_code[j + 1]) uf_unite(i, j + 1);
    } else {
        r -= 31*1024;
        int b = r >> 10, y = r & 1023;
        int x = 32*b + 31;
        int i = base + (y << 10) + x;
        if (!g_code[i]) return;
        if (g_code[i + 1]) uf_unite(i, i + 1);
        if ((y & 31) != 0  && g_code[i + 1 - IW]) uf_unite(i, i + 1 - IW);
        if ((y & 31) != 31 && g_code[i + 1 + IW]) uf_unite(i, i + 1 + IW);
    }
}

// =================================================================
__global__ __launch_bounds__(256) void k_flatten() {
    int t = blockIdx.x * blockDim.x + threadIdx.x;
    if (t >= NP/4) return;
    uchar4 c = reinterpret_cast<const uchar4*>(g_code)[t];
    int i0 = t * 4;
    if (c.x) { int r = uf_rep(i0);   g_lab[i0]   = r; if (c.x == 2) g_flag[r] = 1; }
    if (c.y) { int r = uf_rep(i0+1); g_lab[i0+1] = r; if (c.y == 2) g_flag[r] = 1; }
    if (c.z) { int r = uf_rep(i0+2); g_lab[i0+2] = r; if (c.z == 2) g_flag[r] = 1; }
    if (c.w) { int r = uf_rep(i0+3); g_lab[i0+3] = r; if (c.w == 2) g_flag[r] = 1; }
}

__global__ __launch_bounds__(256) void k_final(float* __restrict__ out_hyst) {
    int t = blockIdx.x * blockDim.x + threadIdx.x;
    if (t >= NP/4) return;
    uchar4 c = reinterpret_cast<const uchar4*>(g_code)[t];
    int i0 = t * 4;
    float4 v = make_float4(0.f, 0.f, 0.f, 0.f);
    if (c.x && g_flag[g_lab[i0  ]]) v.x = 1.f;
    if (c.y && g_flag[g_lab[i0+1]]) v.y = 1.f;
    if (c.z && g_flag[g_lab[i0+2]]) v.z = 1.f;
    if (c.w && g_flag[g_lab[i0+3]]) v.w = 1.f;
    reinterpret_cast<float4*>(out_hyst)[t] = v;
}

// =================================================================
extern "C" void kernel_launch(void* const* d_in, const int* in_sizes, int n_in,
                              void* d_out, int out_size) {
    const float* img = (const float*)d_in[0];
    float* out = (float*)d_out;

    dim3 fgrid(IW/32, IH/32, NIMG);
    k_front<<<fgrid, 256>>>(img, out);

    const int T = 256;
    k_boundary<<<(NIMG*PER_IMG + T - 1)/T, T>>>();
    k_flatten<<<(NP/4 + T - 1)/T, T>>>();
    k_final<<<(NP/4 + T - 1)/T, T>>>(out + NP);
}

// round 6
// speedup vs baseline: 2.0745x; 1.1505x over previous
#include <cuda_runtime.h>
#include <stdint.h>

#define IW 1024
#define IH 1024
#define NIMG 8
#define PLANE (IW*IH)
#define NP (NIMG*PLANE)

// tile 64 wide x 32 high, 512 threads, 4 px/thread
#define TW 64
#define TH 32
#define NT 512
#define GYW 72   // gray width  (TW+8)
#define GYH 40   // gray height (TH+8)
#define HBW 68   // hblur/vblur width (TW+4)
#define MGW 66   // mag width   (TW+2)

// ---- persistent scratch ----
__device__ unsigned char g_code[NP];
__device__ int           g_lab[NP];
__device__ unsigned char g_flag[NP];

__device__ __constant__ float GW[5] = {
    0.0544886855f, 0.2442013420f, 0.4026199447f, 0.2442013420f, 0.0544886855f };

__device__ __constant__ int NDY[8] = {0,-1,-1,-1, 0, 1, 1, 1};
__device__ __constant__ int NDX[8] = {1, 1, 0,-1,-1,-1, 0, 1};

// ---------- shared-memory union-find ----------
__device__ __forceinline__ int rep_s(volatile int* L, int x) {
    int r = L[x];
    int p = L[r];
    while (p != r) { r = p; p = L[r]; }
    return r;
}
__device__ __forceinline__ void unite_s(int* L, int a, int b) {
    volatile int* Lv = L;
    int ra = rep_s(Lv, a), rb = rep_s(Lv, b);
    while (ra != rb) {
        if (ra < rb) { int t = ra; ra = rb; rb = t; }
        int old = atomicMin(&L[ra], rb);
        if (old == ra) break;
        ra = rep_s(Lv, old);
        rb = rep_s(Lv, rb);
    }
}

// ---------- global union-find ----------
__device__ __forceinline__ int uf_rep(int x) {
    volatile int* L = g_lab;
    int r = L[x];
    int p = L[r];
    while (p != r) { r = p; p = L[r]; }
    return r;
}
__device__ __forceinline__ void uf_unite(int a, int b) {
    int ra = uf_rep(a), rb = uf_rep(b);
    while (ra != rb) {
        if (ra < rb) { int t = ra; ra = rb; rb = t; }
        int old = atomicMin(&g_lab[ra], rb);
        if (old == ra) break;
        ra = uf_rep(old);
        rb = uf_rep(rb);
    }
}

// =================================================================
// Fused front (64x32 tile, 512 threads) — flat R3-style loops,
// aliased smem: V->A (gray dead), mag->B (hblur dead), L->A (vblur dead)
// =================================================================
__global__ __launch_bounds__(NT) void k_front(const float* __restrict__ img,
                                              float* __restrict__ out_mag) {
    __shared__ float A[GYH*GYW];           // gray -> vblur(36x68) -> L
    __shared__ float B[GYH*HBW];           // hblur -> mag(34x66)
    __shared__ unsigned char DIR[TH*TW];
    __shared__ unsigned char C[TH*TW];
    float* V = A;                          // vblur aliases gray
    int*   L = reinterpret_cast<int*>(A);  // labels alias vblur

    const int tid = threadIdx.x;
    const int x0 = blockIdx.x * TW;
    const int y0 = blockIdx.y * TH;
    const int n  = blockIdx.z;
    const float* rch = img + (size_t)n * 3 * PLANE;
    const float* gch = rch + PLANE;
    const float* bch = gch + PLANE;

    // ---- stage 1: gray (40x72), reflect pad ----
    for (int i = tid; i < GYH*GYW; i += NT) {
        int ly = i / GYW, lx = i - ly*GYW;
        int gy = y0 + ly - 4;
        int gx = x0 + lx - 4;
        gy = (gy < 0) ? -gy : ((gy >= IH) ? 2*IH - 2 - gy : gy);
        gx = (gx < 0) ? -gx : ((gx >= IW) ? 2*IW - 2 - gx : gx);
        int o = (gy << 10) + gx;
        A[i] = 0.299f * rch[o] + 0.587f * gch[o] + 0.114f * bch[o];
    }
    __syncthreads();

    // ---- stage 2: horizontal blur (40x68) into B ----
    for (int i = tid; i < GYH*HBW; i += NT) {
        int ly = i / HBW, hx = i - ly*HBW;
        float acc = 0.f;
#pragma unroll
        for (int k = 0; k < 5; k++)
            acc = fmaf(GW[k], A[ly*GYW + hx + k], acc);
        B[i] = acc;
    }
    __syncthreads();

    // ---- stage 3: vertical blur (36x68) into V (aliases A) ----
    // row i/HBW of V corresponds to gray row +2; safe in-place? No — V
    // aliases A which stage 3 no longer reads (it reads B only). OK.
    for (int i = tid; i < (TH+4)*HBW; i += NT) {
        int by = i / HBW, bx = i - by*HBW;
        float acc = 0.f;
#pragma unroll
        for (int k = 0; k < 5; k++)
            acc = fmaf(GW[k], B[(by + k)*HBW + bx], acc);
        V[i] = acc;
    }
    __syncthreads();

    // ---- stage 4: sobel + magnitude (34x66) into B, dir (32x64) ----
    // B (hblur) is dead after stage 3; mag overwrites it.
    for (int i = tid; i < (TH+2)*MGW; i += NT) {
        int my = i / MGW, mx = i - my*MGW;
        int gy = y0 + my - 1;
        int gx = x0 + mx - 1;
        float m = 0.f;
        if (gy >= 0 && gy < IH && gx >= 0 && gx < IW) {
            int ym = (gy > 0)    ? gy - 1 : 0;
            int yp = (gy < IH-1) ? gy + 1 : IH - 1;
            int xm = (gx > 0)    ? gx - 1 : 0;
            int xp = (gx < IW-1) ? gx + 1 : IW - 1;
            int lym = ym - y0 + 2, lyc = gy - y0 + 2, lyp = yp - y0 + 2;
            int lxm = xm - x0 + 2, lxc = gx - x0 + 2, lxp = xp - x0 + 2;
            float a = V[lym*HBW+lxm], b = V[lym*HBW+lxc], c = V[lym*HBW+lxp];
            float d = V[lyc*HBW+lxm],                      e = V[lyc*HBW+lxp];
            float f = V[lyp*HBW+lxm], g = V[lyp*HBW+lxc], h = V[lyp*HBW+lxp];
            float gxv = (c - a) + 2.f * (e - d) + (h - f);
            float gyv = (f - a) + 2.f * (g - b) + (h - c);
            m = sqrtf(gxv * gxv + gyv * gyv + 1e-6f);
            if (my >= 1 && my <= TH && mx >= 1 && mx <= TW) {
                float deg = atan2f(gyv, gxv) * 57.29577951308232f;
                int it = (int)rintf(deg / 45.0f);
                DIR[(my-1)*TW + (mx-1)] = (unsigned char)((it + 8) & 7);
            }
        }
        B[i] = m;
    }
    __syncthreads();

    // ---- stage 5: NMS + thresholds; seed local CCL (L aliases V/A) ----
    for (int i = tid; i < TH*TW; i += NT) {
        int cy = i >> 6, cx = i & (TW-1);
        int my = cy + 1, mx = cx + 1;
        float m = B[my*MGW + mx];
        int d  = DIR[i];
        int d2 = (d + 4) & 7;
        float mp = B[(my + NDY[d ])*MGW + (mx + NDX[d ])];
        float mn = B[(my + NDY[d2])*MGW + (mx + NDX[d2])];
        bool keep = ((m - mp) > 0.f) && ((m - mn) > 0.f);
        float mo = keep ? m : 0.f;
        unsigned char code = (unsigned char)((mo > 0.1f ? 1 : 0) + (mo > 0.2f ? 1 : 0));
        int gy = y0 + cy, gx = x0 + cx;
        int idx = n * PLANE + (gy << 10) + gx;
        out_mag[idx] = mo;
        g_code[idx]  = code;
        C[i] = code;
        L[i] = i;
    }
    __syncthreads();

    // ---- stage 6: tile-local union-find hooking ----
    for (int i = tid; i < TH*TW; i += NT) {
        if (!C[i]) continue;
        int cx = i & (TW-1), cy = i >> 6;
        if (cx < TW-1 && C[i + 1])      unite_s(L, i, i + 1);
        if (cy < TH-1) {
            if (cx > 0    && C[i + TW - 1]) unite_s(L, i, i + TW - 1);
            if (             C[i + TW    ]) unite_s(L, i, i + TW);
            if (cx < TW-1 && C[i + TW + 1]) unite_s(L, i, i + TW + 1);
        }
    }
    __syncthreads();

    // ---- stage 7: resolve tile roots, write global labels ----
    for (int i = tid; i < TH*TW; i += NT) {
        if (!C[i]) continue;
        int r = i, p = L[r];
        while (p != r) { r = p; p = L[r]; }
        int gy = y0 + (i >> 6), gx = x0 + (i & (TW-1));
        int idx = n * PLANE + (gy << 10) + gx;
        int ry = y0 + (r >> 6), rx = x0 + (r & (TW-1));
        g_lab[idx]  = n * PLANE + (ry << 10) + rx;
        g_flag[idx] = 0;
    }
}

// =================================================================
// Boundary merge: rows y=32b+31 (31/img), cols x=64b+63 (15/img)
// =================================================================
#define NHROW 31
#define NVCOL 15
#define PER_IMG ((NHROW + NVCOL)*1024)
__global__ __launch_bounds__(256) void k_boundary() {
    int t = blockIdx.x * blockDim.x + threadIdx.x;
    if (t >= NIMG * PER_IMG) return;
    int n = t / PER_IMG;
    int r = t - n * PER_IMG;
    int base = n * PLANE;
    if (r < NHROW*1024) {
        int b = r >> 10, x = r & 1023;
        int y = TH*b + (TH-1);
        int i = base + (y << 10) + x;
        if (!g_code[i]) return;
        int j = i + IW;
        if (x > 0    && g_code[j - 1]) uf_unite(i, j - 1);
        if (            g_code[j    ]) uf_unite(i, j);
        if (x < 1023 && g_code[j + 1]) uf_unite(i, j + 1);
    } else {
        r -= NHROW*1024;
        int b = r >> 10, y = r & 1023;
        int x = TW*b + (TW-1);
        int i = base + (y << 10) + x;
        if (!g_code[i]) return;
        if (g_code[i + 1]) uf_unite(i, i + 1);
        if ((y & (TH-1)) != 0    && g_code[i + 1 - IW]) uf_unite(i, i + 1 - IW);
        if ((y & (TH-1)) != TH-1 && g_code[i + 1 + IW]) uf_unite(i, i + 1 + IW);
    }
}

// =================================================================
__global__ __launch_bounds__(256) void k_flatten() {
    int t = blockIdx.x * blockDim.x + threadIdx.x;
    if (t >= NP/4) return;
    uchar4 c = reinterpret_cast<const uchar4*>(g_code)[t];
    int i0 = t * 4;
    if (c.x) { int r = uf_rep(i0);   g_lab[i0]   = r; if (c.x == 2) g_flag[r] = 1; }
    if (c.y) { int r = uf_rep(i0+1); g_lab[i0+1] = r; if (c.y == 2) g_flag[r] = 1; }
    if (c.z) { int r = uf_rep(i0+2); g_lab[i0+2] = r; if (c.z == 2) g_flag[r] = 1; }
    if (c.w) { int r = uf_rep(i0+3); g_lab[i0+3] = r; if (c.w == 2) g_flag[r] = 1; }
}

__global__ __launch_bounds__(256) void k_final(float* __restrict__ out_hyst) {
    int t = blockIdx.x * blockDim.x + threadIdx.x;
    if (t >= NP/4) return;
    uchar4 c = reinterpret_cast<const uchar4*>(g_code)[t];
    int i0 = t * 4;
    float4 v = make_float4(0.f, 0.f, 0.f, 0.f);
    if (c.x && g_flag[g_lab[i0  ]]) v.x = 1.f;
    if (c.y && g_flag[g_lab[i0+1]]) v.y = 1.f;
    if (c.z && g_flag[g_lab[i0+2]]) v.z = 1.f;
    if (c.w && g_flag[g_lab[i0+3]]) v.w = 1.f;
    reinterpret_cast<float4*>(out_hyst)[t] = v;
}

// =================================================================
extern "C" void kernel_launch(void* const* d_in, const int* in_sizes, int n_in,
                              void* d_out, int out_size) {
    const float* img = (const float*)d_in[0];
    float* out = (float*)d_out;

    dim3 fgrid(IW/TW, IH/TH, NIMG);
    k_front<<<fgrid, NT>>>(img, out);

    const int T = 256;
    k_boundary<<<(NIMG*PER_IMG + T - 1)/T, T>>>();
    k_flatten<<<(NP/4 + T - 1)/T, T>>>();
    k_final<<<(NP/4 + T - 1)/T, T>>>(out + NP);
}

// round 7
// speedup vs baseline: 2.1976x; 1.0593x over previous
#include <cuda_runtime.h>
#include <stdint.h>

#define IW 1024
#define IH 1024
#define NIMG 8
#define PLANE (IW*IH)
#define NP (NIMG*PLANE)

// ---- persistent scratch ----
__device__ int           g_lab[NP];   // -1 = off; else parent (tile root, then UF chain)
__device__ unsigned char g_flag[NP];  // 1 at strong tile roots; hoisted to final roots

__device__ __constant__ float GW[5] = {
    0.0544886855f, 0.2442013420f, 0.4026199447f, 0.2442013420f, 0.0544886855f };

__device__ __constant__ int NDY[8] = {0,-1,-1,-1, 0, 1, 1, 1};
__device__ __constant__ int NDX[8] = {1, 1, 0,-1,-1,-1, 0, 1};

// ---------- shared-memory union-find ----------
__device__ __forceinline__ int rep_s(volatile int* L, int x) {
    int r = L[x];
    int p = L[r];
    while (p != r) { r = p; p = L[r]; }
    return r;
}
__device__ __forceinline__ void unite_s(int* L, int a, int b) {
    volatile int* Lv = L;
    int ra = rep_s(Lv, a), rb = rep_s(Lv, b);
    while (ra != rb) {
        if (ra < rb) { int t = ra; ra = rb; rb = t; }
        int old = atomicMin(&L[ra], rb);
        if (old == ra) break;
        ra = rep_s(Lv, old);
        rb = rep_s(Lv, rb);
    }
}

// ---------- global union-find ----------
__device__ __forceinline__ int uf_rep(int x) {
    volatile int* L = g_lab;
    int r = L[x];
    int p = L[r];
    while (p != r) { r = p; p = L[r]; }
    return r;
}
__device__ __forceinline__ void uf_unite(int a, int b) {
    int ra = uf_rep(a), rb = uf_rep(b);
    while (ra != rb) {
        if (ra < rb) { int t = ra; ra = rb; rb = t; }
        int old = atomicMin(&g_lab[ra], rb);
        if (old == ra) break;
        ra = uf_rep(old);
        rb = uf_rep(rb);
    }
}

// =================================================================
// Fused front (32x32 tile, 256 threads) — R3 champion structure
// =================================================================
__global__ __launch_bounds__(256) void k_front(const float* __restrict__ img,
                                               float* __restrict__ out_mag) {
    __shared__ float A[40*40];            // gray, then vblur (36x36)
    __shared__ float B[40*36];            // hblur, then mag (34x34)
    __shared__ unsigned char DIR[32*32];  // dir, then strong-root flags
    __shared__ unsigned char C[32*32];    // code 0/1/2
    __shared__ int L[32*32];

    const int tid = threadIdx.x;
    const int x0 = blockIdx.x * 32;
    const int y0 = blockIdx.y * 32;
    const int n  = blockIdx.z;
    const float* rch = img + (size_t)n * 3 * PLANE;
    const float* gch = rch + PLANE;
    const float* bch = gch + PLANE;

    // ---- stage 1: gray (40x40), reflect pad ----
    for (int i = tid; i < 40*40; i += 256) {
        int ly = i / 40, lx = i - ly*40;
        int gy = y0 + ly - 4;
        int gx = x0 + lx - 4;
        gy = (gy < 0) ? -gy : ((gy >= IH) ? 2*IH - 2 - gy : gy);
        gx = (gx < 0) ? -gx : ((gx >= IW) ? 2*IW - 2 - gx : gx);
        int o = (gy << 10) + gx;
        A[i] = 0.299f * rch[o] + 0.587f * gch[o] + 0.114f * bch[o];
    }
    __syncthreads();

    // ---- stage 2: horizontal blur (40 rows x 36 cols) ----
    for (int i = tid; i < 40*36; i += 256) {
        int ly = i / 36, hx = i - ly*36;
        float acc = 0.f;
#pragma unroll
        for (int k = 0; k < 5; k++)
            acc = fmaf(GW[k], A[ly*40 + hx + k], acc);
        B[i] = acc;
    }
    __syncthreads();

    // ---- stage 3: vertical blur (36x36) into A ----
    for (int i = tid; i < 36*36; i += 256) {
        int by = i / 36, bx = i - by*36;
        float acc = 0.f;
#pragma unroll
        for (int k = 0; k < 5; k++)
            acc = fmaf(GW[k], B[(by + k)*36 + bx], acc);
        A[i] = acc;
    }
    __syncthreads();

    // ---- stage 4: sobel + magnitude (34x34) into B, dir (32x32) ----
    for (int i = tid; i < 34*34; i += 256) {
        int my = i / 34, mx = i - my*34;
        int gy = y0 + my - 1;
        int gx = x0 + mx - 1;
        float m = 0.f;
        if (gy >= 0 && gy < IH && gx >= 0 && gx < IW) {
            int ym = (gy > 0)    ? gy - 1 : 0;
            int yp = (gy < IH-1) ? gy + 1 : IH - 1;
            int xm = (gx > 0)    ? gx - 1 : 0;
            int xp = (gx < IW-1) ? gx + 1 : IW - 1;
            int lym = ym - y0 + 2, lyc = gy - y0 + 2, lyp = yp - y0 + 2;
            int lxm = xm - x0 + 2, lxc = gx - x0 + 2, lxp = xp - x0 + 2;
            float a = A[lym*36+lxm], b = A[lym*36+lxc], c = A[lym*36+lxp];
            float d = A[lyc*36+lxm],                     e = A[lyc*36+lxp];
            float f = A[lyp*36+lxm], g = A[lyp*36+lxc], h = A[lyp*36+lxp];
            float gxv = (c - a) + 2.f * (e - d) + (h - f);
            float gyv = (f - a) + 2.f * (g - b) + (h - c);
            m = sqrtf(gxv * gxv + gyv * gyv + 1e-6f);
            if (my >= 1 && my <= 32 && mx >= 1 && mx <= 32) {
                float deg = atan2f(gyv, gxv) * 57.29577951308232f;
                int it = (int)rintf(deg / 45.0f);
                DIR[(my-1)*32 + (mx-1)] = (unsigned char)((it + 8) & 7);
            }
        }
        B[i] = m;
    }
    __syncthreads();

    // ---- stage 5: NMS + thresholds; seed local CCL ----
    for (int i = tid; i < 32*32; i += 256) {
        int cy = i >> 5, cx = i & 31;
        int my = cy + 1, mx = cx + 1;
        float m = B[my*34 + mx];
        int d  = DIR[i];
        int d2 = (d + 4) & 7;
        float mp = B[(my + NDY[d ])*34 + (mx + NDX[d ])];
        float mn = B[(my + NDY[d2])*34 + (mx + NDX[d2])];
        bool keep = ((m - mp) > 0.f) && ((m - mn) > 0.f);
        float mo = keep ? m : 0.f;
        unsigned char code = (unsigned char)((mo > 0.1f ? 1 : 0) + (mo > 0.2f ? 1 : 0));
        int gy = y0 + cy, gx = x0 + cx;
        int idx = n * PLANE + (gy << 10) + gx;
        out_mag[idx] = mo;
        C[i] = code;
        L[i] = i;
    }
    __syncthreads();

    // ---- stage 6: tile-local union-find hooking ----
    for (int i = tid; i < 32*32; i += 256) {
        if (!C[i]) continue;
        int cx = i & 31, cy = i >> 5;
        if (cx < 31 && C[i + 1])  unite_s(L, i, i + 1);
        if (cy < 31) {
            if (cx > 0  && C[i + 31]) unite_s(L, i, i + 31);
            if (           C[i + 32]) unite_s(L, i, i + 32);
            if (cx < 31 && C[i + 33]) unite_s(L, i, i + 33);
        }
    }
    __syncthreads();

    // ---- stage 6.5: per-tile strong flags at local roots (reuse DIR) ----
    for (int i = tid; i < 32*32; i += 256) DIR[i] = 0;
    __syncthreads();
    for (int i = tid; i < 32*32; i += 256) {
        if (C[i] == 2) {
            int r = i, p = L[r];
            while (p != r) { r = p; p = L[r]; }
            DIR[r] = 1;
        }
    }
    __syncthreads();

    // ---- stage 7: write global labels + flags for ALL pixels ----
    for (int i = tid; i < 32*32; i += 256) {
        int gy = y0 + (i >> 5), gx = x0 + (i & 31);
        int idx = n * PLANE + (gy << 10) + gx;
        if (!C[i]) {
            g_lab[idx]  = -1;
            g_flag[idx] = 0;
        } else {
            int r = i, p = L[r];
            while (p != r) { r = p; p = L[r]; }
            int ry = y0 + (r >> 5), rx = x0 + (r & 31);
            g_lab[idx]  = n * PLANE + (ry << 10) + rx;
            g_flag[idx] = (i == r) ? DIR[r] : 0;
        }
    }
}

// =================================================================
// Boundary merge: tile edges only ("on" test = g_lab >= 0)
// =================================================================
#define PER_IMG (31*1024*2)
__global__ __launch_bounds__(256) void k_boundary() {
    int t = blockIdx.x * blockDim.x + threadIdx.x;
    if (t >= NIMG * PER_IMG) return;
    int n = t / PER_IMG;
    int r = t - n * PER_IMG;
    int base = n * PLANE;
    if (r < 31*1024) {
        int b = r >> 10, x = r & 1023;
        int y = 32*b + 31;
        int i = base + (y << 10) + x;
        if (g_lab[i] < 0) return;
        int j = i + IW;
        if (x > 0    && g_lab[j - 1] >= 0) uf_unite(i, j - 1);
        if (            g_lab[j    ] >= 0) uf_unite(i, j);
        if (x < 1023 && g_lab[j + 1] >= 0) uf_unite(i, j + 1);
    } else {
        r -= 31*1024;
        int b = r >> 10, y = r & 1023;
        int x = 32*b + 31;
        int i = base + (y << 10) + x;
        if (g_lab[i] < 0) return;
        if (g_lab[i + 1] >= 0) uf_unite(i, i + 1);
        if ((y & 31) != 0  && g_lab[i + 1 - IW] >= 0) uf_unite(i, i + 1 - IW);
        if ((y & 31) != 31 && g_lab[i + 1 + IW] >= 0) uf_unite(i, i + 1 + IW);
    }
}

// =================================================================
// Propagate strong flags from tile roots to final roots.
// Reads g_flag 16 bytes/thread; sparse chases. Idempotent writes of 1.
// =================================================================
__global__ __launch_bounds__(256) void k_propagate() {
    int t = blockIdx.x * blockDim.x + threadIdx.x;
    if (t >= NP/16) return;
    const uint4* F16 = reinterpret_cast<const uint4*>(g_flag);
    uint4 f = F16[t];
    if ((f.x | f.y | f.z | f.w) == 0u) return;
    int i0 = t * 16;
    unsigned int w[4] = {f.x, f.y, f.z, f.w};
#pragma unroll
    for (int q = 0; q < 4; q++) {
        unsigned int v = w[q];
        if (!v) continue;
#pragma unroll
        for (int b = 0; b < 4; b++) {
            if ((v >> (b*8)) & 0xFFu) {
                int i = i0 + q*4 + b;
                int r = uf_rep(i);
                if (r != i) g_flag[r] = 1;
            }
        }
    }
}

// =================================================================
// Final: chase from tile root (short, cached), read flag at root
// =================================================================
__global__ __launch_bounds__(256) void k_final(float* __restrict__ out_hyst) {
    int t = blockIdx.x * blockDim.x + threadIdx.x;
    if (t >= NP/4) return;
    int4 lb = reinterpret_cast<const int4*>(g_lab)[t];
    float4 v = make_float4(0.f, 0.f, 0.f, 0.f);
    int lab;
    lab = lb.x;
    if (lab >= 0) { int p = g_lab[lab]; while (p != lab) { lab = p; p = g_lab[lab]; }
                    if (g_flag[lab]) v.x = 1.f; }
    lab = lb.y;
    if (lab >= 0) { int p = g_lab[lab]; while (p != lab) { lab = p; p = g_lab[lab]; }
                    if (g_flag[lab]) v.y = 1.f; }
    lab = lb.z;
    if (lab >= 0) { int p = g_lab[lab]; while (p != lab) { lab = p; p = g_lab[lab]; }
                    if (g_flag[lab]) v.z = 1.f; }
    lab = lb.w;
    if (lab >= 0) { int p = g_lab[lab]; while (p != lab) { lab = p; p = g_lab[lab]; }
                    if (g_flag[lab]) v.w = 1.f; }
    reinterpret_cast<float4*>(out_hyst)[t] = v;
}

// =================================================================
extern "C" void kernel_launch(void* const* d_in, const int* in_sizes, int n_in,
                              void* d_out, int out_size) {
    const float* img = (const float*)d_in[0];
    float* out = (float*)d_out;

    dim3 fgrid(IW/32, IH/32, NIMG);
    k_front<<<fgrid, 256>>>(img, out);

    const int T = 256;
    k_boundary<<<(NIMG*PER_IMG + T - 1)/T, T>>>();
    k_propagate<<<(NP/16 + T - 1)/T, T>>>();
    k_final<<<(NP/4 + T - 1)/T, T>>>(out + NP);
}